// round 10
// baseline (speedup 1.0000x reference)
#include <cuda_runtime.h>
#include <cuda_bf16.h>

#define HIDDEN 128
#define MAX_NODES 131072

__device__ float g_s1[MAX_NODES];
__device__ float g_s2[MAX_NODES];

// 8 lanes per node, 4 nodes per warp.
// Lane l handles node (warp*4 + (l>>3)), columns [(l&7)*... interleaved]:
// float4 index (l&7) + 8j for j=0..3 -> 16 floats/lane, coalesced 128B per
// 8-lane group. Local 16-float dot for both W halves, then 3-stage butterfly
// over the 8-lane group: 6 SHFLs reduce all 4 nodes' two dots at once.
__global__ __launch_bounds__(256)
void node_dot_kernel(const float4* __restrict__ x4,
                     const float4* __restrict__ W4,
                     int n_nodes,
                     float* __restrict__ s1,
                     float* __restrict__ s2) {
    int warp = (blockIdx.x * blockDim.x + threadIdx.x) >> 5;
    int lane = threadIdx.x & 31;
    int sub  = lane & 7;          // position within 8-lane group
    int node = warp * 4 + (lane >> 3);

    // Hoist W slices (same for all loop-free work; depends only on sub)
    float4 wa0 = __ldg(&W4[sub]);
    float4 wa1 = __ldg(&W4[sub + 8]);
    float4 wa2 = __ldg(&W4[sub + 16]);
    float4 wa3 = __ldg(&W4[sub + 24]);
    float4 wb0 = __ldg(&W4[32 + sub]);
    float4 wb1 = __ldg(&W4[32 + sub + 8]);
    float4 wb2 = __ldg(&W4[32 + sub + 16]);
    float4 wb3 = __ldg(&W4[32 + sub + 24]);

    float a = 0.f, c = 0.f;
    bool valid = node < n_nodes;
    if (valid) {
        const float4* p = x4 + (size_t)node * 32 + sub;
        // Front-batch 4 loads (64B/lane)
        float4 v0 = p[0];
        float4 v1 = p[8];
        float4 v2 = p[16];
        float4 v3 = p[24];

        a = v0.x*wa0.x + v0.y*wa0.y + v0.z*wa0.z + v0.w*wa0.w
          + v1.x*wa1.x + v1.y*wa1.y + v1.z*wa1.z + v1.w*wa1.w
          + v2.x*wa2.x + v2.y*wa2.y + v2.z*wa2.z + v2.w*wa2.w
          + v3.x*wa3.x + v3.y*wa3.y + v3.z*wa3.z + v3.w*wa3.w;
        c = v0.x*wb0.x + v0.y*wb0.y + v0.z*wb0.z + v0.w*wb0.w
          + v1.x*wb1.x + v1.y*wb1.y + v1.z*wb1.z + v1.w*wb1.w
          + v2.x*wb2.x + v2.y*wb2.y + v2.z*wb2.z + v2.w*wb2.w
          + v3.x*wb3.x + v3.y*wb3.y + v3.z*wb3.z + v3.w*wb3.w;
    }

    // 3-stage butterfly within each 8-lane group (reduces 4 nodes at once)
    #pragma unroll
    for (int o = 4; o > 0; o >>= 1) {
        a += __shfl_xor_sync(0xFFFFFFFFu, a, o);
        c += __shfl_xor_sync(0xFFFFFFFFu, c, o);
    }

    if (sub == 0 && valid) {
        s1[node] = a;
        s2[node] = c;
    }
}

// out[e] = s1[src[e]] + s2[dst[e]] + b.
// 4 edges/thread, int4 index loads, 8 front-batched gathers. At the L1tex
// divergent-gather wavefront floor; 128-thread blocks for high occupancy.
__global__ __launch_bounds__(128)
void edge_kernel(const int* __restrict__ ei,
                 int n_edges,
                 const float* __restrict__ s1,
                 const float* __restrict__ s2,
                 const float* __restrict__ bptr,
                 float* __restrict__ out) {
    float b = __ldg(bptr);
    int tid = blockIdx.x * blockDim.x + threadIdx.x;
    int base = tid * 4;
    const int* src = ei;
    const int* dst = ei + n_edges;

    if (base + 3 < n_edges) {
        int4 s4 = __ldg((const int4*)(src + base));
        int4 d4 = __ldg((const int4*)(dst + base));

        float v0 = __ldg(&s1[s4.x]);
        float v1 = __ldg(&s1[s4.y]);
        float v2 = __ldg(&s1[s4.z]);
        float v3 = __ldg(&s1[s4.w]);
        float u0 = __ldg(&s2[d4.x]);
        float u1 = __ldg(&s2[d4.y]);
        float u2 = __ldg(&s2[d4.z]);
        float u3 = __ldg(&s2[d4.w]);

        float4 r = make_float4(v0 + u0 + b, v1 + u1 + b,
                               v2 + u2 + b, v3 + u3 + b);
        *(float4*)(out + base) = r;
    } else {
        for (int e = base; e < n_edges; e++) {
            out[e] = __ldg(&s1[src[e]]) + __ldg(&s2[dst[e]]) + b;
        }
    }
}

extern "C" void kernel_launch(void* const* d_in, const int* in_sizes, int n_in,
                              void* d_out, int out_size) {
    const float* x  = (const float*)d_in[0];   // (n_nodes, 128) f32
    const int*   ei = (const int*)d_in[1];     // (2, n_edges) int32
    const float* W  = (const float*)d_in[2];   // (1, 256) f32
    const float* b  = (const float*)d_in[3];   // (1,) f32
    float* out = (float*)d_out;

    int n_nodes = in_sizes[0] / HIDDEN;
    int n_edges = in_sizes[1] / 2;

    float* s1;
    float* s2;
    cudaGetSymbolAddress((void**)&s1, g_s1);
    cudaGetSymbolAddress((void**)&s2, g_s2);

    // Kernel 1: 4 nodes per warp (8 lanes/node)
    {
        int threads = 256;                          // 8 warps/block
        int nodes_per_block = (threads / 32) * 4;   // 32
        int blocks = (n_nodes + nodes_per_block - 1) / nodes_per_block;
        node_dot_kernel<<<blocks, threads>>>((const float4*)x, (const float4*)W,
                                             n_nodes, s1, s2);
    }

    // Kernel 2: 4 edges/thread, 128-thread blocks
    {
        int threads = 128;
        int edges_per_block = threads * 4;
        int blocks = (n_edges + edges_per_block - 1) / edges_per_block;
        edge_kernel<<<blocks, threads>>>(ei, n_edges, s1, s2, b, out);
    }
}